// round 1
// baseline (speedup 1.0000x reference)
#include <cuda_runtime.h>
#include <math.h>

#define EPSR 1e-6f

// ---------------- smem layout (floats) ----------------
#define PITCH 204                       // 196 + 8, 16B-aligned rows, bank-conflict-free (12*l mod 32 distinct)
#define OFF_S 0                         // 196*204 = 39984
#define OFF_OV 39984                    // overlay region: 12544 (Tc during build; small arrays later)
#define OFF_P (OFF_OV + 12544)          // 52528 : P [196][4]
#define OFF_Q (OFF_P + 784)             // 53312 : Q [196][4]
#define OFF_B (OFF_Q + 784)             // sB [14][4]
#define OFF_C (OFF_B + 56)              // sC [14][4]
#define OFF_BTB (OFF_C + 56)
#define OFF_CTC (OFF_BTB + 16)
#define OFF_ATA (OFF_CTC + 16)
#define OFF_GI (OFF_ATA + 16)
#define OFF_M (OFF_GI + 16)             // sM [14][4]
#define SMEM_FLOATS (OFF_M + 56)        // 54328 floats = 217312 bytes
// overlay internals
#define OV_QPART 0                      // 196*2*4 = 1568
#define OV_REDA 1568                    // 224
#define OV_SY2 1792                     // 512
#define OV_RED 2304                     // 512
#define OV_SZ 2816                      // 32
#define OV_SG 2848                      // 512

// ---------------- f32x2 packed FMA helpers (sm_100+) ----------------
__device__ __forceinline__ unsigned long long pk2(float lo, float hi) {
    unsigned long long r;
    asm("mov.b64 %0, {%1, %2};" : "=l"(r) : "f"(lo), "f"(hi));
    return r;
}
__device__ __forceinline__ void upk2(unsigned long long v, float& lo, float& hi) {
    asm("mov.b64 {%0, %1}, %2;" : "=f"(lo), "=f"(hi) : "l"(v));
}
__device__ __forceinline__ void ffma2(unsigned long long& acc, unsigned long long a, unsigned long long b) {
    asm("fma.rn.f32x2 %0, %1, %2, %0;" : "+l"(acc) : "l"(a), "l"(b));
}

// 4x4 inverse, unpivoted Gauss-Jordan (G is SPD: Schur product of Grams + eps*I)
__device__ __forceinline__ void inv4(const float* __restrict__ G, float* __restrict__ out) {
    float a[4][4], v[4][4];
#pragma unroll
    for (int i = 0; i < 4; i++) {
#pragma unroll
        for (int j = 0; j < 4; j++) { a[i][j] = G[i * 4 + j]; v[i][j] = (i == j) ? 1.f : 0.f; }
    }
#pragma unroll
    for (int c = 0; c < 4; c++) {
        float piv = 1.f / a[c][c];
#pragma unroll
        for (int j = 0; j < 4; j++) { a[c][j] *= piv; v[c][j] *= piv; }
#pragma unroll
        for (int r = 0; r < 4; r++) {
            if (r == c) continue;
            float f = a[r][c];
#pragma unroll
            for (int j = 0; j < 4; j++) { a[r][j] -= f * a[c][j]; v[r][j] -= f * v[c][j]; }
        }
    }
#pragma unroll
    for (int i = 0; i < 4; i++)
#pragma unroll
        for (int j = 0; j < 4; j++) out[i * 4 + j] = v[i][j];
}

extern __shared__ float sm[];

__global__ void __launch_bounds__(512, 1)
dese_kernel(const float* __restrict__ x, const float* __restrict__ B0,
            const float* __restrict__ C0, const float* __restrict__ w1,
            const float* __restrict__ w2, const float* __restrict__ fw1,
            const float* __restrict__ fw2, float* __restrict__ out)
{
    const int b = blockIdx.x;
    const int t = threadIdx.x;

    float* S = sm + OFF_S;
    float* OV = sm + OFF_OV;
    float* P = sm + OFF_P;
    float* Q = sm + OFF_Q;
    float* sB = sm + OFF_B;
    float* sC = sm + OFF_C;
    float* sBtB = sm + OFF_BTB;
    float* sCtC = sm + OFF_CTC;
    float* sAtA = sm + OFF_ATA;
    float* sGi = sm + OFF_GI;
    float* sM = sm + OFF_M;

    const float* xs = x + (size_t)b * 100352;   // this sample's T0: [512][196] row-major

    // ================= Phase 1: S = T0^T T0 (upper-tri 8x8 tiles, FFMA2) =================
    int tp = 0, tq = 0;
    const bool tact = (t < 325);
    if (tact) {
        int id = t, row = 0;
        while (id >= 25 - row) { id -= 25 - row; ++row; }
        tp = row; tq = row + id;                 // tp <= tq, 25x26/2 = 325 tiles
    }
    unsigned long long acc[32];
#pragma unroll
    for (int i = 0; i < 32; i++) acc[i] = 0ULL;

    float* Tc = OV;                              // 64 x 196 chunk staging
    for (int ch = 0; ch < 8; ch++) {
        {
            const float4* src = (const float4*)(xs + ch * 12544);
            float4* dst = (float4*)Tc;
            for (int v = t; v < 3136; v += 512) dst[v] = src[v];
        }
        __syncthreads();
        if (tact) {
#pragma unroll 2
            for (int i = 0; i < 64; i++) {
                const float* row = Tc + i * 196;
                float4 pA = *(const float4*)(row + tp * 8);
                float4 pB = *(const float4*)(row + tp * 8 + 4);
                float4 qA = *(const float4*)(row + tq * 8);
                float4 qB = *(const float4*)(row + tq * 8 + 4);
                unsigned long long qb0 = pk2(qA.x, qA.y);
                unsigned long long qb1 = pk2(qA.z, qA.w);
                unsigned long long qb2 = pk2(qB.x, qB.y);
                unsigned long long qb3 = pk2(qB.z, qB.w);
                float pv[8] = {pA.x, pA.y, pA.z, pA.w, pB.x, pB.y, pB.z, pB.w};
#pragma unroll
                for (int p = 0; p < 8; p++) {
                    unsigned long long pd = pk2(pv[p], pv[p]);
                    ffma2(acc[p * 4 + 0], pd, qb0);
                    ffma2(acc[p * 4 + 1], pd, qb1);
                    ffma2(acc[p * 4 + 2], pd, qb2);
                    ffma2(acc[p * 4 + 3], pd, qb3);
                }
            }
        }
        __syncthreads();
    }
    if (tact) {
#pragma unroll
        for (int p = 0; p < 8; p++) {
            int gp = tp * 8 + p;
            if (gp < 196) {
#pragma unroll
                for (int qp = 0; qp < 4; qp++) {
                    float lo, hi;
                    upk2(acc[p * 4 + qp], lo, hi);
                    int gq = tq * 8 + qp * 2;
                    if (gq < 196) { S[gp * PITCH + gq] = lo; if (tp != tq) S[gq * PITCH + gp] = lo; }
                    if (gq + 1 < 196) { S[gp * PITCH + gq + 1] = hi; if (tp != tq) S[(gq + 1) * PITCH + gp] = hi; }
                }
            }
        }
    }
    // init factors (A0 is mathematically unused by the reference: A is overwritten first)
    if (t < 56) sB[t] = B0[b * 56 + t];
    else if (t < 112) sC[t - 56] = C0[b * 56 + (t - 56)];
    __syncthreads();

    // ================= Phase 2: 20 ALS iterations on S =================
    float* Qpart = OV + OV_QPART;
    float* redA = OV + OV_REDA;

    for (int it = 0; it < 20; it++) {
        // Grams BtB, CtC
        if (t < 32) {
            int which = t >> 4, e = t & 15, a = e >> 2, c2 = e & 3;
            const float* F = which ? sC : sB;
            float s = 0.f;
#pragma unroll
            for (int j = 0; j < 14; j++) s += F[j * 4 + a] * F[j * 4 + c2];
            (which ? sCtC : sBtB)[e] = s;
        }
        __syncthreads();
        if (t == 0) {
            float G[16];
#pragma unroll
            for (int e = 0; e < 16; e++) G[e] = sBtB[e] * sCtC[e] + ((e % 5 == 0) ? EPSR : 0.f);
            inv4(G, sGi);
        }
        __syncthreads();
        // P = KR(B,C) @ GinvA  (so A = T0 @ P)
        if (t < 196) {
            int j = t / 14, k = t - j * 14;
            float kr0 = sB[j * 4 + 0] * sC[k * 4 + 0];
            float kr1 = sB[j * 4 + 1] * sC[k * 4 + 1];
            float kr2 = sB[j * 4 + 2] * sC[k * 4 + 2];
            float kr3 = sB[j * 4 + 3] * sC[k * 4 + 3];
#pragma unroll
            for (int r = 0; r < 4; r++)
                P[t * 4 + r] = kr0 * sGi[0 * 4 + r] + kr1 * sGi[1 * 4 + r] +
                               kr2 * sGi[2 * 4 + r] + kr3 * sGi[3 * 4 + r];
        }
        __syncthreads();
        // Q = S @ P  (= T0^T A, exact). 392 threads: warp-contiguous rows, q split by h.
        if (t < 392) {
            int p = (t < 196) ? t : (t - 196);
            int h = (t < 196) ? 0 : 1;
            int q0 = h ? 96 : 0, q1 = h ? 196 : 96;
            float a0 = 0, a1 = 0, a2 = 0, a3 = 0;
            const float* srow = S + p * PITCH;
            for (int q = q0; q < q1; q += 4) {
                float4 sv = *(const float4*)(srow + q);
                float4 p0 = *(const float4*)(P + (q + 0) * 4);
                float4 p1 = *(const float4*)(P + (q + 1) * 4);
                float4 p2 = *(const float4*)(P + (q + 2) * 4);
                float4 p3 = *(const float4*)(P + (q + 3) * 4);
                a0 += sv.x * p0.x + sv.y * p1.x + sv.z * p2.x + sv.w * p3.x;
                a1 += sv.x * p0.y + sv.y * p1.y + sv.z * p2.y + sv.w * p3.y;
                a2 += sv.x * p0.z + sv.y * p1.z + sv.z * p2.z + sv.w * p3.z;
                a3 += sv.x * p0.w + sv.y * p1.w + sv.z * p2.w + sv.w * p3.w;
            }
            Qpart[p * 8 + h * 4 + 0] = a0;
            Qpart[p * 8 + h * 4 + 1] = a1;
            Qpart[p * 8 + h * 4 + 2] = a2;
            Qpart[p * 8 + h * 4 + 3] = a3;
        }
        __syncthreads();
        if (t < 196) {
#pragma unroll
            for (int r = 0; r < 4; r++)
                Q[t * 4 + r] = Qpart[t * 8 + r] + Qpart[t * 8 + 4 + r];
        }
        __syncthreads();
        // AtA = P^T Q (partials) ; M1[j,r] = sum_k C[k,r] Q[j*14+k, r]
        if (t < 224) {
            int e = t / 14, c = t - (t / 14) * 14;
            int s_ = e >> 2, r = e & 3;
            float v = 0.f;
            int pb = c * 14;
#pragma unroll
            for (int p = 0; p < 14; p++) v += P[(pb + p) * 4 + s_] * Q[(pb + p) * 4 + r];
            redA[e * 14 + c] = v;
        } else if (t >= 256 && t < 312) {
            int e = t - 256; int j = e >> 2, r = e & 3;
            float v = 0.f;
#pragma unroll
            for (int k = 0; k < 14; k++) v += sC[k * 4 + r] * Q[(j * 14 + k) * 4 + r];
            sM[e] = v;
        }
        __syncthreads();
        if (t < 16) {
            float v = 0.f;
#pragma unroll
            for (int c = 0; c < 14; c++) v += redA[t * 14 + c];
            sAtA[t] = v;
        }
        __syncthreads();
        if (t == 0) {
            float G[16];
#pragma unroll
            for (int e = 0; e < 16; e++) G[e] = sAtA[e] * sCtC[e] + ((e % 5 == 0) ? EPSR : 0.f);
            inv4(G, sGi);
        }
        __syncthreads();
        // B = M1 @ GinvB
        if (t < 56) {
            int j = t >> 2, r = t & 3;
            sB[t] = sM[j * 4 + 0] * sGi[0 * 4 + r] + sM[j * 4 + 1] * sGi[1 * 4 + r] +
                    sM[j * 4 + 2] * sGi[2 * 4 + r] + sM[j * 4 + 3] * sGi[3 * 4 + r];
        }
        __syncthreads();
        // BtB (new) ; M2[k,r] = sum_j B_new[j,r] Q[j*14+k, r]
        if (t < 16) {
            int a = t >> 2, c2 = t & 3;
            float s = 0.f;
#pragma unroll
            for (int j = 0; j < 14; j++) s += sB[j * 4 + a] * sB[j * 4 + c2];
            sBtB[t] = s;
        } else if (t >= 64 && t < 120) {
            int e = t - 64; int k = e >> 2, r = e & 3;
            float v = 0.f;
#pragma unroll
            for (int j = 0; j < 14; j++) v += sB[j * 4 + r] * Q[(j * 14 + k) * 4 + r];
            sM[e] = v;
        }
        __syncthreads();
        if (t == 0) {
            float G[16];
#pragma unroll
            for (int e = 0; e < 16; e++) G[e] = sAtA[e] * sBtB[e] + ((e % 5 == 0) ? EPSR : 0.f);
            inv4(G, sGi);
        }
        __syncthreads();
        // C = M2 @ GinvC
        if (t < 56) {
            int k = t >> 2, r = t & 3;
            sC[t] = sM[k * 4 + 0] * sGi[0 * 4 + r] + sM[k * 4 + 1] * sGi[1 * 4 + r] +
                    sM[k * 4 + 2] * sGi[2 * 4 + r] + sM[k * 4 + 3] * sGi[3 * 4 + r];
        }
        __syncthreads();
    }

    // ================= Phase 3: A = T0 @ P_final, rank_fc, SE, gate =================
    float* sy2 = OV + OV_SY2;
    float* red = OV + OV_RED;
    float* sz = OV + OV_SZ;
    float* sg = OV + OV_SG;

    {   // thread t = channel i; P (last A-step projection) still in smem
        const float* xrow = xs + t * 196;
        float a0 = 0, a1 = 0, a2 = 0, a3 = 0;
        for (int q = 0; q < 196; q += 4) {
            float4 xv = *(const float4*)(xrow + q);
            a0 += xv.x * P[(q + 0) * 4 + 0] + xv.y * P[(q + 1) * 4 + 0] + xv.z * P[(q + 2) * 4 + 0] + xv.w * P[(q + 3) * 4 + 0];
            a1 += xv.x * P[(q + 0) * 4 + 1] + xv.y * P[(q + 1) * 4 + 1] + xv.z * P[(q + 2) * 4 + 1] + xv.w * P[(q + 3) * 4 + 1];
            a2 += xv.x * P[(q + 0) * 4 + 2] + xv.y * P[(q + 1) * 4 + 2] + xv.z * P[(q + 2) * 4 + 2] + xv.w * P[(q + 3) * 4 + 2];
            a3 += xv.x * P[(q + 0) * 4 + 3] + xv.y * P[(q + 1) * 4 + 3] + xv.z * P[(q + 2) * 4 + 3] + xv.w * P[(q + 3) * 4 + 3];
        }
        float y2 = 0.f;
#pragma unroll
        for (int s_ = 0; s_ < 4; s_++) {
            float u = a0 * w1[s_ * 4 + 0] + a1 * w1[s_ * 4 + 1] + a2 * w1[s_ * 4 + 2] + a3 * w1[s_ * 4 + 3];
            u = fmaxf(u, 0.f);
            y2 += u * w2[s_];
        }
        sy2[t] = y2;
    }
    __syncthreads();
    {   // z = relu(fw1 @ y2) : 32 outputs, 16-way partials
        int m = t >> 4, c = t & 15;
        const float* fr = fw1 + m * 512 + c * 32;
        const float* yy = sy2 + c * 32;
        float v = 0.f;
#pragma unroll
        for (int i2 = 0; i2 < 32; i2++) v += fr[i2] * yy[i2];
        red[m * 16 + c] = v;
    }
    __syncthreads();
    if (t < 32) {
        float v = 0.f;
#pragma unroll
        for (int c = 0; c < 16; c++) v += red[t * 16 + c];
        sz[t] = fmaxf(v, 0.f);
    }
    __syncthreads();
    {   // g = sigmoid(fw2 @ z)
        const float* fr = fw2 + t * 32;
        float v = 0.f;
#pragma unroll
        for (int m = 0; m < 32; m++) v += fr[m] * sz[m];
        sg[t] = 1.f / (1.f + expf(-v));
    }
    __syncthreads();
    {   // out = x * g[channel], coalesced float4
        const float4* xin4 = (const float4*)xs;
        float4* out4 = (float4*)(out + (size_t)b * 100352);
        for (int v = t; v < 25088; v += 512) {
            float g = sg[v / 49];               // 49 float4 per channel row
            float4 xv = xin4[v];
            out4[v] = make_float4(xv.x * g, xv.y * g, xv.z * g, xv.w * g);
        }
    }
}

extern "C" void kernel_launch(void* const* d_in, const int* in_sizes, int n_in,
                              void* d_out, int out_size) {
    const float* x   = (const float*)d_in[0];
    // d_in[1] = A0: unused (reference overwrites A before first use)
    const float* B0  = (const float*)d_in[2];
    const float* C0  = (const float*)d_in[3];
    const float* w1  = (const float*)d_in[4];
    const float* w2  = (const float*)d_in[5];
    const float* fw1 = (const float*)d_in[6];
    const float* fw2 = (const float*)d_in[7];
    float* out = (float*)d_out;

    int b = in_sizes[0] / 100352;                        // 256
    size_t smem = (size_t)SMEM_FLOATS * sizeof(float);   // 217312 B
    cudaFuncSetAttribute(dese_kernel, cudaFuncAttributeMaxDynamicSharedMemorySize, (int)smem);
    dese_kernel<<<b, 512, smem>>>(x, B0, C0, w1, w2, fw1, fw2, out);
}